// round 16
// baseline (speedup 1.0000x reference)
#include <cuda_runtime.h>
#include <cuda_fp16.h>
#include <cstdint>

#define C 128
#define KC 27
#define NLOW_MAX 50000
#define NLOW_BITS 50176
#define WPK (NLOW_BITS / 32)             // 1568
#define TOT_WORDS (KC * WPK)             // 42336
#define NHIGH_MAX 200000
#define E_MAX 1000000
#define SCAN_ELEMS 2048
#define NBLK_MAX ((NHIGH_MAX + SCAN_ELEMS - 1) / SCAN_ELEMS)   // 98
#define SLOT_MAX (KC * 50176)
#define NPERS 148

__device__ unsigned g_xh[(size_t)NLOW_MAX * 64];       // 12.8 MB fp16 fragment-major
__device__ unsigned g_wh[(size_t)KC * C * 64];         // 884 KB
__device__ __half2  g_yc[(size_t)SLOT_MAX * 64];       // 346.8 MB compact Y

__device__ unsigned g_mask[TOT_WORDS];
__device__ int g_cj[SLOT_MAX];
__device__ int g_wpre[TOT_WORDS];
__device__ int g_kcntc[KC];
__device__ int g_koffc[KC];
__device__ int g_blk_k[2048];
__device__ int g_blk_c0[2048];
__device__ int g_blk_nc[2048];
__device__ int g_nblk;
__device__ int g_done;
__device__ int g_ready;
__device__ int g_ticket;

__device__ int g_jk[E_MAX];
__device__ int g_icnt[NHIGH_MAX];
__device__ int g_istart[NHIGH_MAX];
__device__ int g_icur[NHIGH_MAX];
__device__ int g_bsum[NBLK_MAX + 1];

__device__ __forceinline__ void mma_f16(float c[4],
                                        unsigned a0, unsigned a1, unsigned a2, unsigned a3,
                                        unsigned b0, unsigned b1) {
    asm volatile(
        "mma.sync.aligned.m16n8k16.row.col.f32.f16.f16.f32 "
        "{%0,%1,%2,%3}, {%4,%5,%6,%7}, {%8,%9}, {%0,%1,%2,%3};\n"
        : "+f"(c[0]), "+f"(c[1]), "+f"(c[2]), "+f"(c[3])
        : "r"(a0), "r"(a1), "r"(a2), "r"(a3), "r"(b0), "r"(b1));
}

__device__ __forceinline__ void cpa16(unsigned saddr, const void* gptr) {
    asm volatile("cp.async.cg.shared.global [%0], [%1], 16;"
                 :: "r"(saddr), "l"(gptr) : "memory");
}

// ---- prep: pack X + W (R12 gather form, coalesced writes) + zero counters ----
__global__ void prep_kernel(const float* __restrict__ X, const float* __restrict__ W,
                            int Nlow, int NH) {
    int idx = blockIdx.x * blockDim.x + threadIdx.x;
    if (idx < Nlow * 64) {
        int row = idx >> 6, w = idx & 63;
        int tg = w >> 4, r2 = w & 15, kb = r2 >> 1, h = r2 & 1;
        int c0 = 16 * kb + 2 * tg + 8 * h;
        const float* src = X + (size_t)row * C + c0;
        __half2 v = __float22half2_rn(make_float2(src[0], src[1]));
        g_xh[idx] = *(unsigned*)&v;
    }
    if (idx < KC * C * 64) {
        int row = idx >> 6, w = idx & 63;
        int tg = w >> 4, r2 = w & 15, kb = r2 >> 1, h = r2 & 1;
        int c0 = 16 * kb + 2 * tg + 8 * h;
        const float* src = W + (size_t)row * C + c0;
        __half2 v = __float22half2_rn(make_float2(src[0], src[1]));
        g_wh[idx] = *(unsigned*)&v;
    }
    if (idx < NH) g_icnt[idx] = 0;
    if (idx < TOT_WORDS) g_mask[idx] = 0u;
    if (idx == 0) { g_done = 0; g_ready = 0; g_ticket = 0; }
}

// ---- per edge: i-histogram + bitmask claim, 4 edges/thread via int4 ----
__global__ void claimhist_kernel(const int* __restrict__ ih, const int* __restrict__ jl,
                                 const int* __restrict__ kc, int E) {
    int t = blockIdx.x * blockDim.x + threadIdx.x;
    int e4 = t * 4;
    if (e4 + 3 < E) {
        int4 i4 = *(const int4*)(ih + e4);
        int4 j4 = *(const int4*)(jl + e4);
        int4 k4 = *(const int4*)(kc + e4);
        atomicAdd(&g_icnt[i4.x], 1);
        atomicAdd(&g_icnt[i4.y], 1);
        atomicAdd(&g_icnt[i4.z], 1);
        atomicAdd(&g_icnt[i4.w], 1);
        int a = k4.x * NLOW_BITS + j4.x;
        int b = k4.y * NLOW_BITS + j4.y;
        int c = k4.z * NLOW_BITS + j4.z;
        int d = k4.w * NLOW_BITS + j4.w;
        atomicOr(&g_mask[a >> 5], 1u << (a & 31));
        atomicOr(&g_mask[b >> 5], 1u << (b & 31));
        atomicOr(&g_mask[c >> 5], 1u << (c & 31));
        atomicOr(&g_mask[d >> 5], 1u << (d & 31));
    } else {
        for (int e = e4; e < E; e++) {
            atomicAdd(&g_icnt[ih[e]], 1);
            int kj = kc[e] * NLOW_BITS + jl[e];
            atomicOr(&g_mask[kj >> 5], 1u << (kj & 31));
        }
    }
}

// ---- per-k popc scan + parallel descriptor build + FUSED fill ----
// 27 blocks, all co-resident on 148 SMs -> ready-flag spin is deadlock-free
__global__ void kscan_kernel() {
    __shared__ int tsum[16], woff[16];
    __shared__ int sCh[32], sDk[32];
    __shared__ int sLast;
    int k = blockIdx.x, tid = threadIdx.x;
    int lane = tid & 31, wid = tid >> 5;
    const unsigned* mw = g_mask + k * WPK;
    int w0 = tid * 4;
    unsigned mword[4];
    int c[4], s = 0;
#pragma unroll
    for (int u = 0; u < 4; u++) {
        mword[u] = (w0 + u < WPK) ? mw[w0 + u] : 0u;
        c[u] = __popc(mword[u]);
        s += c[u];
    }
    int incl = s;
#pragma unroll
    for (int o = 1; o < 32; o <<= 1) {
        int n = __shfl_up_sync(~0u, incl, o);
        if (lane >= o) incl += n;
    }
    if (lane == 31) tsum[wid] = incl;
    __syncthreads();
    if (tid == 0) {
        int run = 0;
        for (int w = 0; w < 16; w++) { int t = tsum[w]; woff[w] = run; run += t; }
        g_kcntc[k] = run;
    }
    __syncthreads();
    int pre0 = woff[wid] + (incl - s);
    {
        int pre = pre0;
#pragma unroll
        for (int u = 0; u < 4; u++) {
            if (w0 + u < WPK) { g_wpre[k * WPK + w0 + u] = pre; pre += c[u]; }
        }
    }
    __threadfence();
    __syncthreads();
    if (tid == 0) {
        int prev = atomicAdd(&g_done, 1);
        sLast = (prev == KC - 1) ? 1 : 0;
    }
    __syncthreads();

    if (sLast) {
        // parallel offsets + descriptor build (warp 0 scans, all threads write)
        if (tid < 32) {
            int cnt = (tid < KC) ? g_kcntc[tid] : 0;
            int ch = (cnt + 127) >> 7;
            int nd = (ch + 7) >> 3;
            int a = ch << 7, b = nd;
#pragma unroll
            for (int o = 1; o < 32; o <<= 1) {
                int na = __shfl_up_sync(~0u, a, o);
                int nb = __shfl_up_sync(~0u, b, o);
                if (lane >= o) { a += na; b += nb; }
            }
            sCh[tid] = ch;
            sDk[tid] = b - nd;               // exclusive desc offset
            if (tid < KC) g_koffc[tid] = a - (ch << 7);
            if (tid == KC - 1) g_nblk = b;   // total descriptors
        }
        __syncthreads();
        int nb = sDk[KC - 1] + ((sCh[KC - 1] + 7) >> 3);
        for (int t = tid; t < nb; t += 512) {
            int kk = 0;
            for (int q = 1; q < KC; q++)
                if (sDk[q] <= t) kk = q;
            int c0 = (t - sDk[kk]) * 8;
            int rem = sCh[kk] - c0;
            g_blk_k[t] = kk;
            g_blk_c0[t] = c0;
            g_blk_nc[t] = rem < 8 ? rem : 8;
        }
        __threadfence();
        __syncthreads();
        if (tid == 0) atomicExch(&g_ready, 1);
    } else {
        if (tid == 0) {
            while (atomicAdd(&g_ready, 0) == 0) { }
        }
        __syncthreads();
        __threadfence();
    }

    // fused fill: expand this block's mask words into cj
    int pos = g_koffc[k] + pre0;
#pragma unroll
    for (int u = 0; u < 4; u++) {
        unsigned m = mword[u];
        int j0 = (w0 + u) * 32;
        while (m) {
            int b = __ffs(m) - 1;
            m &= m - 1;
            g_cj[pos++] = j0 + b;
        }
    }
}

// ---- prefix scan over i-counts ----
__global__ void scan1_kernel(int NH) {
    int tid = threadIdx.x;
    int base = blockIdx.x * SCAN_ELEMS + tid * 4;
    int s = 0;
#pragma unroll
    for (int u = 0; u < 4; u++) { int i = base + u; if (i < NH) s += g_icnt[i]; }
#pragma unroll
    for (int o = 16; o; o >>= 1) s += __shfl_down_sync(~0u, s, o);
    __shared__ int ws[16];
    if ((tid & 31) == 0) ws[tid >> 5] = s;
    __syncthreads();
    if (tid == 0) {
        int t = 0;
        for (int w = 0; w < 16; w++) t += ws[w];
        g_bsum[blockIdx.x] = t;
    }
}

__global__ void scan2_kernel(int nb) {
    __shared__ int sh[NBLK_MAX];
    int tid = threadIdx.x;
    if (tid < nb) sh[tid] = g_bsum[tid];
    __syncthreads();
    if (tid == 0) {
        int run = 0;
        for (int b = 0; b < nb; b++) { int t = sh[b]; sh[b] = run; run += t; }
    }
    __syncthreads();
    if (tid < nb) g_bsum[tid] = sh[tid];
}

__global__ void scan3_kernel(int NH) {
    int tid = threadIdx.x;
    int lane = tid & 31, wid = tid >> 5;
    int base = blockIdx.x * SCAN_ELEMS + tid * 4;
    int v[4], ts = 0;
#pragma unroll
    for (int u = 0; u < 4; u++) {
        int i = base + u;
        v[u] = (i < NH) ? g_icnt[i] : 0;
        ts += v[u];
    }
    int incl = ts;
#pragma unroll
    for (int o = 1; o < 32; o <<= 1) {
        int n = __shfl_up_sync(~0u, incl, o);
        if (lane >= o) incl += n;
    }
    __shared__ int wtot[16], woff[16];
    if (lane == 31) wtot[wid] = incl;
    __syncthreads();
    if (tid == 0) {
        int run = 0;
        for (int w = 0; w < 16; w++) { int t = wtot[w]; woff[w] = run; run += t; }
    }
    __syncthreads();
    int pre = g_bsum[blockIdx.x] + woff[wid] + (incl - ts);
#pragma unroll
    for (int u = 0; u < 4; u++) {
        int i = base + u;
        if (i < NH) { g_istart[i] = pre; g_icur[i] = pre; pre += v[u]; }
    }
}

// ---- rank edges; compute compact pos from bitmask ----
__global__ void rank_kernel(const int* __restrict__ ih, const int* __restrict__ jl,
                            const int* __restrict__ kc, int E) {
    int e = blockIdx.x * blockDim.x + threadIdx.x;
    if (e >= E) return;
    int rank = atomicAdd(&g_icur[ih[e]], 1);
    int k = kc[e];
    int kj = k * NLOW_BITS + jl[e];
    int w = kj >> 5, bit = kj & 31;
    int pos = g_koffc[k] + g_wpre[w] + __popc(g_mask[w] & ((1u << bit) - 1u));
    g_jk[rank] = pos;
}

// ---- compacted gather-GEMM, persistent work-stealing (frozen R15) ----
#define STR 80
#define AT_WORDS (128 * STR)
#define SMEM_BYTES (4 * AT_WORDS * 4 + 16)

__device__ __forceinline__ void stage_A(unsigned sbuf, int slotBase, int sr, int stg) {
    int j = g_cj[slotBase + sr];
    const unsigned* src = g_xh + (size_t)j * 64 + stg * 16;
    unsigned dst = sbuf + (sr * STR + stg * 20) * 4;
#pragma unroll
    for (int q = 0; q < 4; q++)
        cpa16(dst + q * 16, src + q * 4);
}

__global__ void __launch_bounds__(512, 1) gemm_kernel() {
    extern __shared__ unsigned smem[];
    unsigned* Ws = smem;
    unsigned* Ab[3] = { smem + AT_WORDS, smem + 2 * AT_WORDS, smem + 3 * AT_WORDS };
    int* sTicket = (int*)(smem + 4 * AT_WORDS);
    const int tid = threadIdx.x;

    unsigned sW = (unsigned)__cvta_generic_to_shared(Ws);
    unsigned sA[3] = { (unsigned)__cvta_generic_to_shared(Ab[0]),
                       (unsigned)__cvta_generic_to_shared(Ab[1]),
                       (unsigned)__cvta_generic_to_shared(Ab[2]) };

    const int sr = tid >> 2, stg = tid & 3;
    const int warp = tid >> 5, lane = tid & 31;
    const int g = lane >> 2, tg = lane & 3;
    const int rowBase = (warp >> 2) * 32;
    const int coBase  = (warp & 3) * 32;
    const int bOff = ((coBase + g) * STR + tg * 20) / 4;
    const int ntStride = (8 * STR) / 4;
    const uint4* Bp = (const uint4*)Ws + bOff;
    const int nblk = g_nblk;

    for (;;) {
        if (tid == 0) *sTicket = atomicAdd(&g_ticket, 1);
        asm volatile("cp.async.wait_group 0;" ::: "memory");
        __syncthreads();
        int b = *sTicket;
        if (b >= nblk) break;

        const int k  = g_blk_k[b];
        const int c0 = g_blk_c0[b];
        const int nc = g_blk_nc[b];
        const int base = g_koffc[k] + c0 * 128;

        {
            const unsigned* wsrc = g_wh + ((size_t)k * 128 + sr) * 64 + stg * 16;
            unsigned dW = sW + (sr * STR + stg * 20) * 4;
#pragma unroll
            for (int q = 0; q < 4; q++)
                cpa16(dW + q * 16, wsrc + q * 4);
            stage_A(sA[0], base, sr, stg);
        }
        asm volatile("cp.async.commit_group;");
        if (nc > 1) stage_A(sA[1], base + 128, sr, stg);
        asm volatile("cp.async.commit_group;");

        for (int t = 0; t < nc; t++) {
            asm volatile("cp.async.wait_group 1;" ::: "memory");
            __syncthreads();

            if (t + 2 < nc) stage_A(sA[(t + 2) % 3], base + (t + 2) * 128, sr, stg);
            asm volatile("cp.async.commit_group;");

            unsigned* Ax = Ab[t % 3];
            const uint4* A0 = (const uint4*)(Ax + (rowBase + g     ) * STR + tg * 20);
            const uint4* A1 = (const uint4*)(Ax + (rowBase + g +  8) * STR + tg * 20);
            const uint4* A2 = (const uint4*)(Ax + (rowBase + g + 16) * STR + tg * 20);
            const uint4* A3 = (const uint4*)(Ax + (rowBase + g + 24) * STR + tg * 20);

            float acc[2][4][4];
#pragma unroll
            for (int mt = 0; mt < 2; mt++)
#pragma unroll
                for (int nt = 0; nt < 4; nt++) {
                    acc[mt][nt][0] = 0.f; acc[mt][nt][1] = 0.f;
                    acc[mt][nt][2] = 0.f; acc[mt][nt][3] = 0.f;
                }

#pragma unroll
            for (int q = 0; q < 4; q++) {
                uint4 a0 = A0[q];
                uint4 a1 = A1[q];
                uint4 a2 = A2[q];
                uint4 a3 = A3[q];
                uint4 b0 = Bp[0 * ntStride + q];
                uint4 b1 = Bp[1 * ntStride + q];
                uint4 b2 = Bp[2 * ntStride + q];
                uint4 b3 = Bp[3 * ntStride + q];
                mma_f16(acc[0][0], a0.x, a1.x, a0.y, a1.y, b0.x, b0.y);
                mma_f16(acc[0][1], a0.x, a1.x, a0.y, a1.y, b1.x, b1.y);
                mma_f16(acc[0][2], a0.x, a1.x, a0.y, a1.y, b2.x, b2.y);
                mma_f16(acc[0][3], a0.x, a1.x, a0.y, a1.y, b3.x, b3.y);
                mma_f16(acc[1][0], a2.x, a3.x, a2.y, a3.y, b0.x, b0.y);
                mma_f16(acc[1][1], a2.x, a3.x, a2.y, a3.y, b1.x, b1.y);
                mma_f16(acc[1][2], a2.x, a3.x, a2.y, a3.y, b2.x, b2.y);
                mma_f16(acc[1][3], a2.x, a3.x, a2.y, a3.y, b3.x, b3.y);
                mma_f16(acc[0][0], a0.z, a1.z, a0.w, a1.w, b0.z, b0.w);
                mma_f16(acc[0][1], a0.z, a1.z, a0.w, a1.w, b1.z, b1.w);
                mma_f16(acc[0][2], a0.z, a1.z, a0.w, a1.w, b2.z, b2.w);
                mma_f16(acc[0][3], a0.z, a1.z, a0.w, a1.w, b3.z, b3.w);
                mma_f16(acc[1][0], a2.z, a3.z, a2.w, a3.w, b0.z, b0.w);
                mma_f16(acc[1][1], a2.z, a3.z, a2.w, a3.w, b1.z, b1.w);
                mma_f16(acc[1][2], a2.z, a3.z, a2.w, a3.w, b2.z, b2.w);
                mma_f16(acc[1][3], a2.z, a3.z, a2.w, a3.w, b3.z, b3.w);
            }

            int posBase = base + t * 128;
#pragma unroll
            for (int mt = 0; mt < 2; mt++) {
                int r0 = rowBase + mt * 16 + g;
#pragma unroll
                for (int nt = 0; nt < 4; nt++) {
                    int co2 = (coBase + nt * 8 + 2 * tg) >> 1;
                    g_yc[(size_t)(posBase + r0) * 64 + co2] =
                        __float22half2_rn(make_float2(acc[mt][nt][0], acc[mt][nt][1]));
                    g_yc[(size_t)(posBase + r0 + 8) * 64 + co2] =
                        __float22half2_rn(make_float2(acc[mt][nt][2], acc[mt][nt][3]));
                }
            }
        }
        __syncthreads();
    }
}

// ---- segmented sum: warp per output row, 4-way MLP (frozen R15) ----
__global__ void segsum_kernel(float* __restrict__ out, const float* __restrict__ bias,
                              int NH) {
    int gw = (blockIdx.x * blockDim.x + threadIdx.x) >> 5;
    int lane = threadIdx.x & 31;
    if (gw >= NH) return;
    int start = g_istart[gw];
    int cnt = g_icnt[gw];
    float4 acc = ((const float4*)bias)[lane];
    const char* ybase = (const char*)g_yc;
    int r = 0;
    for (; r + 4 <= cnt; r += 4) {
        int p0 = g_jk[start + r];
        int p1 = g_jk[start + r + 1];
        int p2 = g_jk[start + r + 2];
        int p3 = g_jk[start + r + 3];
        uint2 v0 = *(const uint2*)(ybase + (size_t)p0 * 256 + lane * 8);
        uint2 v1 = *(const uint2*)(ybase + (size_t)p1 * 256 + lane * 8);
        uint2 v2 = *(const uint2*)(ybase + (size_t)p2 * 256 + lane * 8);
        uint2 v3 = *(const uint2*)(ybase + (size_t)p3 * 256 + lane * 8);
        float2 a0 = __half22float2(*(const __half2*)&v0.x);
        float2 b0 = __half22float2(*(const __half2*)&v0.y);
        float2 a1 = __half22float2(*(const __half2*)&v1.x);
        float2 b1 = __half22float2(*(const __half2*)&v1.y);
        float2 a2 = __half22float2(*(const __half2*)&v2.x);
        float2 b2 = __half22float2(*(const __half2*)&v2.y);
        float2 a3 = __half22float2(*(const __half2*)&v3.x);
        float2 b3 = __half22float2(*(const __half2*)&v3.y);
        acc.x += (a0.x + a1.x) + (a2.x + a3.x);
        acc.y += (a0.y + a1.y) + (a2.y + a3.y);
        acc.z += (b0.x + b1.x) + (b2.x + b3.x);
        acc.w += (b0.y + b1.y) + (b2.y + b3.y);
    }
    for (; r < cnt; r++) {
        int p0 = g_jk[start + r];
        uint2 v0 = *(const uint2*)(ybase + (size_t)p0 * 256 + lane * 8);
        float2 a = __half22float2(*(const __half2*)&v0.x);
        float2 b = __half22float2(*(const __half2*)&v0.y);
        acc.x += a.x; acc.y += a.y; acc.z += b.x; acc.w += b.y;
    }
    ((float4*)out)[(size_t)gw * 32 + lane] = acc;
}

extern "C" void kernel_launch(void* const* d_in, const int* in_sizes, int n_in,
                              void* d_out, int out_size) {
    const float* x    = (const float*)d_in[0];
    const float* w    = (const float*)d_in[1];
    const float* bias = (const float*)d_in[2];
    const int* ih     = (const int*)d_in[3];
    const int* jl     = (const int*)d_in[4];
    const int* kc     = (const int*)d_in[5];
    float* out = (float*)d_out;

    const int Nlow = in_sizes[0] / C;          // 50000
    const int E    = in_sizes[3];              // 1,000,000
    const int NH   = out_size / C;             // 200,000
    const int nbScan = (NH + SCAN_ELEMS - 1) / SCAN_ELEMS;

    static cudaStream_t s2 = nullptr;
    static cudaEvent_t evFork = nullptr, evJoin = nullptr;
    if (s2 == nullptr) {
        cudaStreamCreateWithFlags(&s2, cudaStreamNonBlocking);
        cudaEventCreateWithFlags(&evFork, cudaEventDisableTiming);
        cudaEventCreateWithFlags(&evJoin, cudaEventDisableTiming);
    }

    int prepTot = Nlow * 64;
    prep_kernel<<<(prepTot + 255) / 256, 256>>>(x, w, Nlow, NH);
    claimhist_kernel<<<(E / 4 + 255) / 256, 256>>>(ih, jl, kc, E);
    kscan_kernel<<<KC, 512>>>();               // scan + offsets + descriptors + fill

    // fork: scans+rank on s2, GEMM on main
    cudaEventRecord(evFork, 0);
    cudaStreamWaitEvent(s2, evFork, 0);
    scan1_kernel<<<nbScan, 512, 0, s2>>>(NH);
    scan2_kernel<<<1, 128, 0, s2>>>(nbScan);
    scan3_kernel<<<nbScan, 512, 0, s2>>>(NH);
    rank_kernel<<<(E + 255) / 256, 256, 0, s2>>>(ih, jl, kc, E);
    cudaEventRecord(evJoin, s2);

    cudaFuncSetAttribute(gemm_kernel, cudaFuncAttributeMaxDynamicSharedMemorySize,
                         SMEM_BYTES);
    gemm_kernel<<<NPERS, 512, SMEM_BYTES>>>();

    cudaStreamWaitEvent(0, evJoin, 0);
    long long sthreads = (long long)NH * 32;
    segsum_kernel<<<(int)((sthreads + 255) / 256), 256>>>(out, bias, NH);
}

// round 17
// speedup vs baseline: 1.0268x; 1.0268x over previous
#include <cuda_runtime.h>
#include <cuda_fp16.h>
#include <cstdint>

#define C 128
#define KC 27
#define NLOW_MAX 50000
#define NLOW_BITS 50176
#define WPK (NLOW_BITS / 32)             // 1568
#define TOT_WORDS (KC * WPK)             // 42336
#define NHIGH_MAX 200000
#define E_MAX 1000000
#define SCAN_ELEMS 2048
#define NBLK_MAX ((NHIGH_MAX + SCAN_ELEMS - 1) / SCAN_ELEMS)   // 98
#define SLOT_MAX (KC * 50176)
#define NPERS 148

__device__ unsigned g_xh[(size_t)NLOW_MAX * 64];       // 12.8 MB fp16 fragment-major
__device__ unsigned g_wh[(size_t)KC * C * 64];         // 884 KB
__device__ __half2  g_yc[(size_t)SLOT_MAX * 64];       // 346.8 MB compact Y

__device__ unsigned g_mask[TOT_WORDS];   // zero at load; re-zeroed by segsum each call
__device__ int g_wpre[TOT_WORDS];
__device__ int g_cj[SLOT_MAX];
__device__ int g_kcntc[KC];
__device__ int g_koffc[KC];
__device__ int g_blk_k[2048];
__device__ int g_blk_c0[2048];
__device__ int g_blk_nc[2048];
__device__ int g_nblk;
__device__ int g_done;                   // reset by fill each call
__device__ int g_ticket;                 // reset by segsum each call

__device__ int g_jk[E_MAX];
__device__ int g_icnt[NHIGH_MAX];        // zero at load; re-zeroed by segsum each call
__device__ int g_istart[NHIGH_MAX];
__device__ int g_icur[NHIGH_MAX];
__device__ int g_bsum[NBLK_MAX + 1];

__device__ __forceinline__ void mma_f16(float c[4],
                                        unsigned a0, unsigned a1, unsigned a2, unsigned a3,
                                        unsigned b0, unsigned b1) {
    asm volatile(
        "mma.sync.aligned.m16n8k16.row.col.f32.f16.f16.f32 "
        "{%0,%1,%2,%3}, {%4,%5,%6,%7}, {%8,%9}, {%0,%1,%2,%3};\n"
        : "+f"(c[0]), "+f"(c[1]), "+f"(c[2]), "+f"(c[3])
        : "r"(a0), "r"(a1), "r"(a2), "r"(a3), "r"(b0), "r"(b1));
}

__device__ __forceinline__ void cpa16(unsigned saddr, const void* gptr) {
    asm volatile("cp.async.cg.shared.global [%0], [%1], 16;"
                 :: "r"(saddr), "l"(gptr) : "memory");
}

// ---- fused pack(X,W) + edge claim/histogram ----
// One thread per pack word (3.2M); every 8th thread also claims 4 edges
// (counters are pre-zeroed by the PREVIOUS call's segsum / load-time BSS zero).
__global__ void packclaim_kernel(const float* __restrict__ X, const float* __restrict__ W,
                                 const int* __restrict__ ih, const int* __restrict__ jl,
                                 const int* __restrict__ kc, int Nlow, int E) {
    int t = blockIdx.x * blockDim.x + threadIdx.x;
    if (t < Nlow * 64) {
        int row = t >> 6, w = t & 63;
        int tg = w >> 4, r2 = w & 15, kb = r2 >> 1, h = r2 & 1;
        int c0 = 16 * kb + 2 * tg + 8 * h;
        const float* src = X + (size_t)row * C + c0;
        __half2 v = __float22half2_rn(make_float2(src[0], src[1]));
        g_xh[t] = *(unsigned*)&v;
    }
    if (t < KC * C * 64) {
        int row = t >> 6, w = t & 63;
        int tg = w >> 4, r2 = w & 15, kb = r2 >> 1, h = r2 & 1;
        int c0 = 16 * kb + 2 * tg + 8 * h;
        const float* src = W + (size_t)row * C + c0;
        __half2 v = __float22half2_rn(make_float2(src[0], src[1]));
        g_wh[t] = *(unsigned*)&v;
    }
    if ((t & 7) == 0) {
        int e4 = (t >> 3) * 4;
        if (e4 + 3 < E) {
            int4 i4 = *(const int4*)(ih + e4);
            int4 j4 = *(const int4*)(jl + e4);
            int4 k4 = *(const int4*)(kc + e4);
            atomicAdd(&g_icnt[i4.x], 1);
            atomicAdd(&g_icnt[i4.y], 1);
            atomicAdd(&g_icnt[i4.z], 1);
            atomicAdd(&g_icnt[i4.w], 1);
            int a = k4.x * NLOW_BITS + j4.x;
            int b = k4.y * NLOW_BITS + j4.y;
            int c = k4.z * NLOW_BITS + j4.z;
            int d = k4.w * NLOW_BITS + j4.w;
            atomicOr(&g_mask[a >> 5], 1u << (a & 31));
            atomicOr(&g_mask[b >> 5], 1u << (b & 31));
            atomicOr(&g_mask[c >> 5], 1u << (c & 31));
            atomicOr(&g_mask[d >> 5], 1u << (d & 31));
        } else if (e4 < E) {
            for (int e = e4; e < E; e++) {
                atomicAdd(&g_icnt[ih[e]], 1);
                int kj = kc[e] * NLOW_BITS + jl[e];
                atomicOr(&g_mask[kj >> 5], 1u << (kj & 31));
            }
        }
    }
}

// ---- per-k popc scan; last block computes offsets + block descriptors (R15) ----
__global__ void kscan_kernel() {
    __shared__ int tsum[16], woff[16];
    int k = blockIdx.x, tid = threadIdx.x;
    int lane = tid & 31, wid = tid >> 5;
    const unsigned* mw = g_mask + k * WPK;
    int w0 = tid * 4;
    int c[4], s = 0;
#pragma unroll
    for (int u = 0; u < 4; u++) {
        c[u] = (w0 + u < WPK) ? __popc(mw[w0 + u]) : 0;
        s += c[u];
    }
    int incl = s;
#pragma unroll
    for (int o = 1; o < 32; o <<= 1) {
        int n = __shfl_up_sync(~0u, incl, o);
        if (lane >= o) incl += n;
    }
    if (lane == 31) tsum[wid] = incl;
    __syncthreads();
    if (tid == 0) {
        int run = 0;
        for (int w = 0; w < 16; w++) { int t = tsum[w]; woff[w] = run; run += t; }
        g_kcntc[k] = run;
    }
    __syncthreads();
    int pre = woff[wid] + (incl - s);
#pragma unroll
    for (int u = 0; u < 4; u++) {
        if (w0 + u < WPK) { g_wpre[k * WPK + w0 + u] = pre; pre += c[u]; }
    }
    __threadfence();
    __syncthreads();
    if (tid == 0) {
        int prev = atomicAdd(&g_done, 1);
        if (prev == KC - 1) {
            int off = 0, nb = 0;
            for (int kk = 0; kk < KC; kk++) {
                g_koffc[kk] = off;
                int ch = (g_kcntc[kk] + 127) >> 7;
                off += ch << 7;
                for (int c0 = 0; c0 < ch; c0 += 8) {
                    g_blk_k[nb] = kk;
                    g_blk_c0[nb] = c0;
                    g_blk_nc[nb] = (ch - c0) < 8 ? (ch - c0) : 8;
                    nb++;
                }
            }
            g_nblk = nb;
        }
    }
}

// ---- build pos -> j table; also resets g_done for the next call ----
__global__ void fill_kernel() {
    int w = blockIdx.x * blockDim.x + threadIdx.x;
    if (w == 0) g_done = 0;
    if (w >= TOT_WORDS) return;
    int k = w / WPK;
    int j0 = (w % WPK) * 32;
    unsigned m = g_mask[w];
    int pos = g_koffc[k] + g_wpre[w];
    while (m) {
        int b = __ffs(m) - 1;
        m &= m - 1;
        g_cj[pos++] = j0 + b;
    }
}

// ---- prefix scan over i-counts ----
__global__ void scan1_kernel(int NH) {
    int tid = threadIdx.x;
    int base = blockIdx.x * SCAN_ELEMS + tid * 4;
    int s = 0;
#pragma unroll
    for (int u = 0; u < 4; u++) { int i = base + u; if (i < NH) s += g_icnt[i]; }
#pragma unroll
    for (int o = 16; o; o >>= 1) s += __shfl_down_sync(~0u, s, o);
    __shared__ int ws[16];
    if ((tid & 31) == 0) ws[tid >> 5] = s;
    __syncthreads();
    if (tid == 0) {
        int t = 0;
        for (int w = 0; w < 16; w++) t += ws[w];
        g_bsum[blockIdx.x] = t;
    }
}

__global__ void scan2_kernel(int nb) {
    __shared__ int sh[NBLK_MAX];
    int tid = threadIdx.x;
    if (tid < nb) sh[tid] = g_bsum[tid];
    __syncthreads();
    if (tid == 0) {
        int run = 0;
        for (int b = 0; b < nb; b++) { int t = sh[b]; sh[b] = run; run += t; }
    }
    __syncthreads();
    if (tid < nb) g_bsum[tid] = sh[tid];
}

__global__ void scan3_kernel(int NH) {
    int tid = threadIdx.x;
    int lane = tid & 31, wid = tid >> 5;
    int base = blockIdx.x * SCAN_ELEMS + tid * 4;
    int v[4], ts = 0;
#pragma unroll
    for (int u = 0; u < 4; u++) {
        int i = base + u;
        v[u] = (i < NH) ? g_icnt[i] : 0;
        ts += v[u];
    }
    int incl = ts;
#pragma unroll
    for (int o = 1; o < 32; o <<= 1) {
        int n = __shfl_up_sync(~0u, incl, o);
        if (lane >= o) incl += n;
    }
    __shared__ int wtot[16], woff[16];
    if (lane == 31) wtot[wid] = incl;
    __syncthreads();
    if (tid == 0) {
        int run = 0;
        for (int w = 0; w < 16; w++) { int t = wtot[w]; woff[w] = run; run += t; }
    }
    __syncthreads();
    int pre = g_bsum[blockIdx.x] + woff[wid] + (incl - ts);
#pragma unroll
    for (int u = 0; u < 4; u++) {
        int i = base + u;
        if (i < NH) { g_istart[i] = pre; g_icur[i] = pre; pre += v[u]; }
    }
}

// ---- rank edges; compute compact pos from bitmask ----
__global__ void rank_kernel(const int* __restrict__ ih, const int* __restrict__ jl,
                            const int* __restrict__ kc, int E) {
    int e = blockIdx.x * blockDim.x + threadIdx.x;
    if (e >= E) return;
    int rank = atomicAdd(&g_icur[ih[e]], 1);
    int k = kc[e];
    int kj = k * NLOW_BITS + jl[e];
    int w = kj >> 5, bit = kj & 31;
    int pos = g_koffc[k] + g_wpre[w] + __popc(g_mask[w] & ((1u << bit) - 1u));
    g_jk[rank] = pos;
}

// ---- compacted gather-GEMM, persistent work-stealing (frozen R15) ----
#define STR 80
#define AT_WORDS (128 * STR)
#define SMEM_BYTES (4 * AT_WORDS * 4 + 16)

__device__ __forceinline__ void stage_A(unsigned sbuf, int slotBase, int sr, int stg) {
    int j = g_cj[slotBase + sr];
    const unsigned* src = g_xh + (size_t)j * 64 + stg * 16;
    unsigned dst = sbuf + (sr * STR + stg * 20) * 4;
#pragma unroll
    for (int q = 0; q < 4; q++)
        cpa16(dst + q * 16, src + q * 4);
}

__global__ void __launch_bounds__(512, 1) gemm_kernel() {
    extern __shared__ unsigned smem[];
    unsigned* Ws = smem;
    unsigned* Ab[3] = { smem + AT_WORDS, smem + 2 * AT_WORDS, smem + 3 * AT_WORDS };
    int* sTicket = (int*)(smem + 4 * AT_WORDS);
    const int tid = threadIdx.x;

    unsigned sW = (unsigned)__cvta_generic_to_shared(Ws);
    unsigned sA[3] = { (unsigned)__cvta_generic_to_shared(Ab[0]),
                       (unsigned)__cvta_generic_to_shared(Ab[1]),
                       (unsigned)__cvta_generic_to_shared(Ab[2]) };

    const int sr = tid >> 2, stg = tid & 3;
    const int warp = tid >> 5, lane = tid & 31;
    const int g = lane >> 2, tg = lane & 3;
    const int rowBase = (warp >> 2) * 32;
    const int coBase  = (warp & 3) * 32;
    const int bOff = ((coBase + g) * STR + tg * 20) / 4;
    const int ntStride = (8 * STR) / 4;
    const uint4* Bp = (const uint4*)Ws + bOff;
    const int nblk = g_nblk;

    for (;;) {
        if (tid == 0) *sTicket = atomicAdd(&g_ticket, 1);
        asm volatile("cp.async.wait_group 0;" ::: "memory");
        __syncthreads();
        int b = *sTicket;
        if (b >= nblk) break;

        const int k  = g_blk_k[b];
        const int c0 = g_blk_c0[b];
        const int nc = g_blk_nc[b];
        const int base = g_koffc[k] + c0 * 128;

        {
            const unsigned* wsrc = g_wh + ((size_t)k * 128 + sr) * 64 + stg * 16;
            unsigned dW = sW + (sr * STR + stg * 20) * 4;
#pragma unroll
            for (int q = 0; q < 4; q++)
                cpa16(dW + q * 16, wsrc + q * 4);
            stage_A(sA[0], base, sr, stg);
        }
        asm volatile("cp.async.commit_group;");
        if (nc > 1) stage_A(sA[1], base + 128, sr, stg);
        asm volatile("cp.async.commit_group;");

        for (int t = 0; t < nc; t++) {
            asm volatile("cp.async.wait_group 1;" ::: "memory");
            __syncthreads();

            if (t + 2 < nc) stage_A(sA[(t + 2) % 3], base + (t + 2) * 128, sr, stg);
            asm volatile("cp.async.commit_group;");

            unsigned* Ax = Ab[t % 3];
            const uint4* A0 = (const uint4*)(Ax + (rowBase + g     ) * STR + tg * 20);
            const uint4* A1 = (const uint4*)(Ax + (rowBase + g +  8) * STR + tg * 20);
            const uint4* A2 = (const uint4*)(Ax + (rowBase + g + 16) * STR + tg * 20);
            const uint4* A3 = (const uint4*)(Ax + (rowBase + g + 24) * STR + tg * 20);

            float acc[2][4][4];
#pragma unroll
            for (int mt = 0; mt < 2; mt++)
#pragma unroll
                for (int nt = 0; nt < 4; nt++) {
                    acc[mt][nt][0] = 0.f; acc[mt][nt][1] = 0.f;
                    acc[mt][nt][2] = 0.f; acc[mt][nt][3] = 0.f;
                }

#pragma unroll
            for (int q = 0; q < 4; q++) {
                uint4 a0 = A0[q];
                uint4 a1 = A1[q];
                uint4 a2 = A2[q];
                uint4 a3 = A3[q];
                uint4 b0 = Bp[0 * ntStride + q];
                uint4 b1 = Bp[1 * ntStride + q];
                uint4 b2 = Bp[2 * ntStride + q];
                uint4 b3 = Bp[3 * ntStride + q];
                mma_f16(acc[0][0], a0.x, a1.x, a0.y, a1.y, b0.x, b0.y);
                mma_f16(acc[0][1], a0.x, a1.x, a0.y, a1.y, b1.x, b1.y);
                mma_f16(acc[0][2], a0.x, a1.x, a0.y, a1.y, b2.x, b2.y);
                mma_f16(acc[0][3], a0.x, a1.x, a0.y, a1.y, b3.x, b3.y);
                mma_f16(acc[1][0], a2.x, a3.x, a2.y, a3.y, b0.x, b0.y);
                mma_f16(acc[1][1], a2.x, a3.x, a2.y, a3.y, b1.x, b1.y);
                mma_f16(acc[1][2], a2.x, a3.x, a2.y, a3.y, b2.x, b2.y);
                mma_f16(acc[1][3], a2.x, a3.x, a2.y, a3.y, b3.x, b3.y);
                mma_f16(acc[0][0], a0.z, a1.z, a0.w, a1.w, b0.z, b0.w);
                mma_f16(acc[0][1], a0.z, a1.z, a0.w, a1.w, b1.z, b1.w);
                mma_f16(acc[0][2], a0.z, a1.z, a0.w, a1.w, b2.z, b2.w);
                mma_f16(acc[0][3], a0.z, a1.z, a0.w, a1.w, b3.z, b3.w);
                mma_f16(acc[1][0], a2.z, a3.z, a2.w, a3.w, b0.z, b0.w);
                mma_f16(acc[1][1], a2.z, a3.z, a2.w, a3.w, b1.z, b1.w);
                mma_f16(acc[1][2], a2.z, a3.z, a2.w, a3.w, b2.z, b2.w);
                mma_f16(acc[1][3], a2.z, a3.z, a2.w, a3.w, b3.z, b3.w);
            }

            int posBase = base + t * 128;
#pragma unroll
            for (int mt = 0; mt < 2; mt++) {
                int r0 = rowBase + mt * 16 + g;
#pragma unroll
                for (int nt = 0; nt < 4; nt++) {
                    int co2 = (coBase + nt * 8 + 2 * tg) >> 1;
                    g_yc[(size_t)(posBase + r0) * 64 + co2] =
                        __float22half2_rn(make_float2(acc[mt][nt][0], acc[mt][nt][1]));
                    g_yc[(size_t)(posBase + r0 + 8) * 64 + co2] =
                        __float22half2_rn(make_float2(acc[mt][nt][2], acc[mt][nt][3]));
                }
            }
        }
        __syncthreads();
    }
}

// ---- segmented sum + state cleanup for next call ----
__global__ void segsum_kernel(float* __restrict__ out, const float* __restrict__ bias,
                              int NH) {
    int gt = blockIdx.x * blockDim.x + threadIdx.x;
    if (gt < TOT_WORDS) g_mask[gt] = 0u;       // restore for next call's claim
    if (gt == 0) g_ticket = 0;
    int gw = gt >> 5;
    int lane = threadIdx.x & 31;
    if (gw >= NH) return;
    int start = g_istart[gw];
    int cnt = g_icnt[gw];
    float4 acc = ((const float4*)bias)[lane];
    const char* ybase = (const char*)g_yc;
    int r = 0;
    for (; r + 4 <= cnt; r += 4) {
        int p0 = g_jk[start + r];
        int p1 = g_jk[start + r + 1];
        int p2 = g_jk[start + r + 2];
        int p3 = g_jk[start + r + 3];
        uint2 v0 = *(const uint2*)(ybase + (size_t)p0 * 256 + lane * 8);
        uint2 v1 = *(const uint2*)(ybase + (size_t)p1 * 256 + lane * 8);
        uint2 v2 = *(const uint2*)(ybase + (size_t)p2 * 256 + lane * 8);
        uint2 v3 = *(const uint2*)(ybase + (size_t)p3 * 256 + lane * 8);
        float2 a0 = __half22float2(*(const __half2*)&v0.x);
        float2 b0 = __half22float2(*(const __half2*)&v0.y);
        float2 a1 = __half22float2(*(const __half2*)&v1.x);
        float2 b1 = __half22float2(*(const __half2*)&v1.y);
        float2 a2 = __half22float2(*(const __half2*)&v2.x);
        float2 b2 = __half22float2(*(const __half2*)&v2.y);
        float2 a3 = __half22float2(*(const __half2*)&v3.x);
        float2 b3 = __half22float2(*(const __half2*)&v3.y);
        acc.x += (a0.x + a1.x) + (a2.x + a3.x);
        acc.y += (a0.y + a1.y) + (a2.y + a3.y);
        acc.z += (b0.x + b1.x) + (b2.x + b3.x);
        acc.w += (b0.y + b1.y) + (b2.y + b3.y);
    }
    for (; r < cnt; r++) {
        int p0 = g_jk[start + r];
        uint2 v0 = *(const uint2*)(ybase + (size_t)p0 * 256 + lane * 8);
        float2 a = __half22float2(*(const __half2*)&v0.x);
        float2 b = __half22float2(*(const __half2*)&v0.y);
        acc.x += a.x; acc.y += a.y; acc.z += b.x; acc.w += b.y;
    }
    ((float4*)out)[(size_t)gw * 32 + lane] = acc;
    __syncwarp();
    if (lane == 0) g_icnt[gw] = 0;             // restore for next call's claim
}

extern "C" void kernel_launch(void* const* d_in, const int* in_sizes, int n_in,
                              void* d_out, int out_size) {
    const float* x    = (const float*)d_in[0];
    const float* w    = (const float*)d_in[1];
    const float* bias = (const float*)d_in[2];
    const int* ih     = (const int*)d_in[3];
    const int* jl     = (const int*)d_in[4];
    const int* kc     = (const int*)d_in[5];
    float* out = (float*)d_out;

    const int Nlow = in_sizes[0] / C;          // 50000
    const int E    = in_sizes[3];              // 1,000,000
    const int NH   = out_size / C;             // 200,000
    const int nbScan = (NH + SCAN_ELEMS - 1) / SCAN_ELEMS;

    static cudaStream_t s2 = nullptr;
    static cudaEvent_t evFork = nullptr, evJoin = nullptr;
    if (s2 == nullptr) {
        cudaStreamCreateWithFlags(&s2, cudaStreamNonBlocking);
        cudaEventCreateWithFlags(&evFork, cudaEventDisableTiming);
        cudaEventCreateWithFlags(&evJoin, cudaEventDisableTiming);
    }

    int pcTot = Nlow * 64;                     // 3.2M threads: pack + spread claims
    packclaim_kernel<<<(pcTot + 255) / 256, 256>>>(x, w, ih, jl, kc, Nlow, E);
    kscan_kernel<<<KC, 512>>>();

    // fork: scans+rank on s2, fill+GEMM on main
    cudaEventRecord(evFork, 0);
    cudaStreamWaitEvent(s2, evFork, 0);
    scan1_kernel<<<nbScan, 512, 0, s2>>>(NH);
    scan2_kernel<<<1, 128, 0, s2>>>(nbScan);
    scan3_kernel<<<nbScan, 512, 0, s2>>>(NH);
    rank_kernel<<<(E + 255) / 256, 256, 0, s2>>>(ih, jl, kc, E);
    cudaEventRecord(evJoin, s2);

    fill_kernel<<<(TOT_WORDS + 255) / 256, 256>>>();
    cudaFuncSetAttribute(gemm_kernel, cudaFuncAttributeMaxDynamicSharedMemorySize,
                         SMEM_BYTES);
    gemm_kernel<<<NPERS, 512, SMEM_BYTES>>>();

    cudaStreamWaitEvent(0, evJoin, 0);
    long long sthreads = (long long)NH * 32;
    segsum_kernel<<<(int)((sthreads + 255) / 256), 256>>>(out, bias, NH);
}